// round 15
// baseline (speedup 1.0000x reference)
#include <cuda_runtime.h>
#include <cstdint>

// Bit-exact XLA:CPU(Eigen) emulation of encoder + |f|^2; fast fp32 decoder.
// e1,e2: per-output sequential FMA chain over k=(kh,kw,ic) ic-fastest,
//        kc=256 panels folded left-assoc with fadd; +bias fadd; relu.
// dot:   single ascending-k FMA chain (K=256 = one Eigen panel).
// dist:  d = fadd(fadd(ff, -(2*dot)), cn); argmin = lowest index on bit-equal.
// Variant A (out1/z_q): ff = 4-lane vector + ordered horizontal.
// Variant B (out0 path): ff = scalar sequential.

#define NB    8
#define CH    256
#define NPIX  (NB * 64 * 64)
#define KC    256

__device__ float g_h  [NB * 128 * 128 * CH];  // NHWC h; reused as dot matrix
__device__ float g_ze [NPIX * CH];            // flat z_e rows; reused as zqB (planar)
__device__ float g_d  [NB * CH * 128 * 128];  // decoder intermediate
__device__ float g_wt [4096 * 256];           // e2 w: [k=(kh*4+kw)*256+ic][oc]
__device__ float g_cn [1024];
__device__ float g_nfA[NPIX], g_nfB[NPIX];
__device__ int   g_codeA[NPIX], g_codeB[NPIX];
#define g_dot g_h
#define g_zqB g_ze

__global__ void k_w2t(const float* __restrict__ w2) {
    int gid = blockIdx.x * 256 + threadIdx.x;     // 1,048,576
    int oc = gid & 255, k = gid >> 8;
    int ic = k & 255, kwh = k >> 8;
    g_wt[gid] = w2[(oc * 256 + ic) * 16 + kwh];
}

// e1 exact chain over (kh,kw); NHWC stores. Block (oh,b); 256 thr = oc.
__global__ __launch_bounds__(256) void k_conv1x(const float* __restrict__ x,
                                                const float* __restrict__ w1,
                                                const float* __restrict__ b1) {
    __shared__ float sx[4][258];
    const int oh = blockIdx.x, b = blockIdx.y, tx = threadIdx.x;
#pragma unroll
    for (int r = 0; r < 4; r++) {
        int ih = 2 * oh - 1 + r;
        for (int c = tx; c < 258; c += 256) {
            int iw = c - 1;
            sx[r][c] = (unsigned(ih) < 256u && unsigned(iw) < 256u)
                           ? x[b * 65536 + ih * 256 + iw] : 0.f;
        }
    }
    __syncthreads();
    const int oc = tx;
    float wreg[16];
#pragma unroll
    for (int t = 0; t < 16; t++) wreg[t] = __ldg(w1 + oc * 16 + t);
    const float bv = __ldg(b1 + oc);
    float* hrow = g_h + (long)((b * 128 + oh) * 128) * 256 + oc;
    for (int ow = 0; ow < 128; ow++) {
        float acc = 0.f;
#pragma unroll
        for (int t = 0; t < 16; t++)
            acc = __fmaf_rn(sx[t >> 2][2 * ow + (t & 3)], wreg[t], acc);
        hrow[(long)ow * 256] = fmaxf(__fadd_rn(acc, bv), 0.f);
    }
}

// e2 exact: 64 ow x 64 oc per block at fixed (b,oh); thread = 4 pix x 4 oc.
// k ascending (kh,kw,ic); fold panel accumulator every KC=256 (each kh,kw).
__global__ __launch_bounds__(256) void k_conv2x(const float* __restrict__ b2) {
    __shared__ float a_s[64][68];   // [pix][ic]
    __shared__ float w_s[64][68];   // [ic][oc]
    const int ocb = blockIdx.x, oh = blockIdx.y, b = blockIdx.z;
    const int tx = threadIdx.x, i = tx >> 4, j = tx & 15;
    float accR[16] = {}, accP[16] = {};

    for (int kh = 0; kh < 4; kh++) {
        const int ih = 2 * oh - 1 + kh;
        const bool okh = (unsigned(ih) < 128u);
        const long hbase = (long)((b * 128 + ih) * 128) * 256;
        for (int kw = 0; kw < 4; kw++) {
            for (int icb = 0; icb < 4; icb++) {
                __syncthreads();
#pragma unroll
                for (int s = 0; s < 4; s++) {
                    int idx = tx + s * 256, pp = idx >> 4, q = idx & 15;
                    int iw = 2 * pp + kw - 1;
                    float4 v = make_float4(0.f, 0.f, 0.f, 0.f);
                    if (okh && unsigned(iw) < 128u)
                        v = *(const float4*)&g_h[hbase + (long)iw * 256 + icb * 64 + q * 4];
                    *(float4*)&a_s[pp][q * 4] = v;
                }
#pragma unroll
                for (int s = 0; s < 4; s++) {
                    int idx = tx + s * 256, ic = idx >> 4, q = idx & 15;
                    *(float4*)&w_s[ic][q * 4] = *(const float4*)
                        &g_wt[(long)((kh * 4 + kw) * 256 + icb * 64 + ic) * 256 + ocb * 64 + q * 4];
                }
                __syncthreads();
#pragma unroll 4
                for (int ic = 0; ic < 64; ic++) {
                    float4 w4 = *(float4*)&w_s[ic][j * 4];
                    float wv[4] = {w4.x, w4.y, w4.z, w4.w};
                    float a[4];
#pragma unroll
                    for (int p = 0; p < 4; p++) a[p] = a_s[i * 4 + p][ic];
#pragma unroll
                    for (int p = 0; p < 4; p++)
#pragma unroll
                        for (int c = 0; c < 4; c++)
                            accP[p * 4 + c] = __fmaf_rn(a[p], wv[c], accP[p * 4 + c]);
                }
            }
            // panel boundary (k multiple of 256): fold
#pragma unroll
            for (int t = 0; t < 16; t++) {
                accR[t] = __fadd_rn(accR[t], accP[t]);
                accP[t] = 0.f;
            }
        }
    }
#pragma unroll
    for (int c = 0; c < 4; c++) {
        float bv = __ldg(b2 + ocb * 64 + j * 4 + c);
#pragma unroll
        for (int p = 0; p < 4; p++) {
            int pix = ((b * 64 + oh) * 64) + i * 4 + p;
            g_ze[(long)pix * 256 + ocb * 64 + j * 4 + c] =
                fmaxf(__fadd_rn(accR[p * 4 + c], bv), 0.f);
        }
    }
}

__global__ void k_cn(const float* __restrict__ cb) {
    int code = blockIdx.x * 256 + threadIdx.x;
    float s = 0.f;
    for (int c = 0; c < CH; c++) { float v = cb[code * CH + c]; s += v * v; }
    g_cn[code] = s;
}

// ff variants: A = 4-lane + ordered horizontal; B = scalar sequential.
__global__ void k_ff() {
    int pix = blockIdx.x * 64 + threadIdx.x;
    const float* f = g_ze + (long)pix * 256;
    float v[4] = {};
    float s = 0.f;
    for (int i = 0; i < 64; i++) {
#pragma unroll
        for (int l = 0; l < 4; l++) {
            float x = __ldg(f + 4 * i + l);
            v[l] = __fadd_rn(v[l], __fmul_rn(x, x));
            s = __fadd_rn(s, __fmul_rn(x, x));
        }
    }
    g_nfA[pix] = __fadd_rn(__fadd_rn(__fadd_rn(v[0], v[1]), v[2]), v[3]);
    g_nfB[pix] = s;
}

// dot GEMM: 64 pix x 64 codes, K=256 ascending single FMA chain per output.
__global__ __launch_bounds__(256) void k_dotg(const float* __restrict__ cb) {
    __shared__ float As[16][68];
    __shared__ float Bs[16][68];
    const int n0 = blockIdx.x * 64, py = blockIdx.y;
    const int tx = threadIdx.x, i = tx >> 4, j = tx & 15;
    const float* fl = g_ze + (long)py * 64 * 256;

    float acc[16] = {};
    for (int kc = 0; kc < 256; kc += 16) {
        __syncthreads();
#pragma unroll
        for (int s = 0; s < 4; s++) {
            int idx = tx + s * 256, p = idx >> 4, k = idx & 15;
            As[k][p] = fl[(long)p * 256 + kc + k];
        }
#pragma unroll
        for (int s = 0; s < 4; s++) {
            int idx = tx + s * 256, n = idx >> 4, k = idx & 15;
            Bs[k][n] = cb[(long)(n0 + n) * 256 + kc + k];
        }
        __syncthreads();
#pragma unroll
        for (int k = 0; k < 16; k++) {
            float4 a4 = *(float4*)&As[k][i * 4];
            float4 c4 = *(float4*)&Bs[k][j * 4];
            float a[4] = {a4.x, a4.y, a4.z, a4.w};
            float c[4] = {c4.x, c4.y, c4.z, c4.w};
#pragma unroll
            for (int p = 0; p < 4; p++)
#pragma unroll
                for (int q = 0; q < 4; q++)
                    acc[p * 4 + q] = __fmaf_rn(a[p], c[q], acc[p * 4 + q]);
        }
    }
#pragma unroll
    for (int p = 0; p < 4; p++) {
        int pix = py * 64 + i * 4 + p;
        float4 v = make_float4(acc[p * 4], acc[p * 4 + 1], acc[p * 4 + 2], acc[p * 4 + 3]);
        *(float4*)&g_dot[(long)pix * 1024 + n0 + j * 4] = v;
    }
}

__device__ __forceinline__ unsigned fkey(float f) {
    unsigned u = __float_as_uint(f);
    return (u & 0x80000000u) ? ~u : (u | 0x80000000u);
}

// d = fadd(fadd(ff, -(2*dot)), cn) bit-exact; lowest index among bit-equal.
__global__ __launch_bounds__(256) void k_amin(int sel) {
    const int pix = blockIdx.x * 8 + (threadIdx.x >> 5);
    const int lane = threadIdx.x & 31;
    const float ff = sel ? g_nfB[pix] : g_nfA[pix];
    const float4* dp = (const float4*)(g_dot + (long)pix * 1024) + lane;

    unsigned long long best = ~0ULL;
#pragma unroll
    for (int s = 0; s < 8; s++) {
        float4 d4 = dp[s * 32];
        float dv[4] = {d4.x, d4.y, d4.z, d4.w};
        int c0 = s * 128 + lane * 4;
#pragma unroll
        for (int q = 0; q < 4; q++) {
            float t = __fadd_rn(ff, -__fmul_rn(2.f, dv[q]));
            float d = __fadd_rn(t, __ldg(g_cn + c0 + q));
            unsigned long long key =
                ((unsigned long long)fkey(d) << 32) | (unsigned)(c0 + q);
            if (key < best) best = key;
        }
    }
#pragma unroll
    for (int m = 16; m >= 1; m >>= 1) {
        unsigned long long o = __shfl_xor_sync(0xffffffffu, best, m);
        if (o < best) best = o;
    }
    if (lane == 0) {
        int* dst = sel ? g_codeB : g_codeA;
        dst[pix] = (int)(best & 0xffffffffu);
    }
}

// planar NCHW gather of z_q from codes
__global__ void k_gather(const float* __restrict__ cb, float* __restrict__ dst, int sel) {
    int gid = blockIdx.x * 256 + threadIdx.x;    // 8,388,608
    int w = gid & 63, hh = (gid >> 6) & 63, c = (gid >> 12) & 255, b = gid >> 20;
    int pix = (b << 12) | (hh << 6) | w;
    int code = sel ? g_codeB[pix] : g_codeA[pix];
    dst[gid] = cb[code * CH + c];
}

// d1: ConvT subpixel; reads g_zqB planar. Block = 128 ow x 64 oc, (b,oh).
__global__ __launch_bounds__(256) void k_dconv1(const float* __restrict__ w,
                                                const float* __restrict__ bias) {
    __shared__ float patch[2][66];
    __shared__ float ws[64][16];
    const int oc0 = blockIdx.x * 64, oh = blockIdx.y, b = blockIdx.z;
    const int a = (oh + 1) & 1;
    const int ih1 = (oh + 1 - a) >> 1;
    const int tx = threadIdx.x, i = tx >> 4, j = tx & 15;
    float acc[8][4] = {};

    for (int ic = 0; ic < CH; ic++) {
        __syncthreads();
        if (tx < 132) {
            int r = tx / 66, c = tx - r * 66;
            int ih = ih1 - 1 + r, iw = c - 1;
            patch[r][c] = (unsigned(ih) < 64u && unsigned(iw) < 64u)
                              ? g_zqB[((b * CH + ic) * 64 + ih) * 64 + iw] : 0.f;
        }
        {
            int ocl = tx & 63, kk = (tx >> 6) << 2;
            *(float4*)&ws[ocl][kk] =
                *(const float4*)&w[((ic * CH + oc0 + ocl) << 4) + kk];
        }
        __syncthreads();
        float r0[6], r1[6];
#pragma unroll
        for (int t = 0; t < 6; t++) { r0[t] = patch[0][4 * i + t]; r1[t] = patch[1][4 * i + t]; }
#pragma unroll
        for (int cc = 0; cc < 4; cc++) {
            float4 wa = *(float4*)&ws[j * 4 + cc][a * 4];
            float4 wb = *(float4*)&ws[j * 4 + cc][(a + 2) * 4];
#pragma unroll
            for (int pp = 0; pp < 8; pp++) {
                int lo = (pp + 1) >> 1, hi = lo + 1;
                float wha, wla, whb, wlb;
                if (pp & 1) { wha = wa.x; wla = wa.z; whb = wb.x; wlb = wb.z; }
                else        { wha = wa.y; wla = wa.w; whb = wb.y; wlb = wb.w; }
                acc[pp][cc] += r1[hi] * wha + r1[lo] * wla + r0[hi] * whb + r0[lo] * wlb;
            }
        }
    }
#pragma unroll
    for (int cc = 0; cc < 4; cc++) {
        int oc = oc0 + j * 4 + cc;
        float bv = bias[oc];
#pragma unroll
        for (int pp = 0; pp < 8; pp++)
            g_d[((b * CH + oc) * 128 + oh) * 128 + i * 8 + pp] =
                fmaxf(acc[pp][cc] + bv, 0.f);
    }
}

__global__ void k_dconv2(const float* __restrict__ w,
                         const float* __restrict__ bias,
                         float* __restrict__ out) {
    __shared__ float patch[2][132];
    __shared__ float wsh[2][4];
    const int oh = blockIdx.x, b = blockIdx.y;
    const int a = (oh + 1) & 1;
    const int ih1 = (oh + 1 - a) >> 1;
    const int tx = threadIdx.x;
    float acc = 0.f;
    for (int ic = 0; ic < CH; ic++) {
        __syncthreads();
        for (int t = tx; t < 260; t += 256) {
            int r = t / 130, c = t - r * 130;
            int ih = ih1 - 1 + r, iw = c - 1;
            patch[r][c] = (unsigned(ih) < 128u && unsigned(iw) < 128u)
                              ? g_d[((b * CH + ic) * 128 + ih) * 128 + iw] : 0.f;
        }
        if (tx < 8) {
            int r = tx >> 2, k = tx & 3;
            wsh[r][k] = w[ic * 16 + (a + 2 * r) * 4 + k];
        }
        __syncthreads();
        int b0 = 1 - (tx & 1);
        int col = ((tx + 1 - b0) >> 1) + 1;
        acc += patch[1][col] * wsh[0][b0] + patch[1][col - 1] * wsh[0][b0 + 2]
             + patch[0][col] * wsh[1][b0] + patch[0][col - 1] * wsh[1][b0 + 2];
    }
    out[(b << 16) + oh * 256 + tx] = acc + bias[0];
}

extern "C" void kernel_launch(void* const* d_in, const int* in_sizes, int n_in,
                              void* d_out, int out_size) {
    const float* x   = (const float*)d_in[0];
    const float* e1w = (const float*)d_in[1];
    const float* e1b = (const float*)d_in[2];
    const float* e2w = (const float*)d_in[3];
    const float* e2b = (const float*)d_in[4];
    const float* cb  = (const float*)d_in[5];
    const float* d1w = (const float*)d_in[6];
    const float* d1b = (const float*)d_in[7];
    const float* d2w = (const float*)d_in[8];
    const float* d2b = (const float*)d_in[9];
    float* out = (float*)d_out;
    float* zq  = out + NB * 256 * 256;

    k_w2t   <<<4096, 256>>>(e2w);
    k_conv1x<<<dim3(128, NB), 256>>>(x, e1w, e1b);
    k_conv2x<<<dim3(4, 64, NB), 256>>>(e2b);
    k_cn    <<<4, 256>>>(cb);
    k_ff    <<<512, 64>>>();
    k_dotg  <<<dim3(16, 512), 256>>>(cb);
    k_amin  <<<4096, 256>>>(0);
    k_amin  <<<4096, 256>>>(1);
    k_gather<<<32768, 256>>>(cb, zq, 0);          // variant A -> out1 (z_q)
    {
        // variant B -> decoder path (g_zqB aliases g_ze; safe after k_dotg)
        float* zqB = nullptr;
        cudaGetSymbolAddress((void**)&zqB, g_ze);
        k_gather<<<32768, 256>>>(cb, zqB, 1);
    }
    k_dconv1<<<dim3(4, 128, NB), 256>>>(d1w, d1b);
    k_dconv2<<<dim3(256, NB), 256>>>(d2w, d2b, out);
}

// round 16
// speedup vs baseline: 2.4194x; 2.4194x over previous
#include <cuda_runtime.h>
#include <cstdint>

// Bit-exact XLA:CPU(Eigen) emulation of encoder + VQ; fast fp32 decoder.
// FFMA2 (fma.rn.f32x2) everywhere hot: per-lane identical rounding to scalar
// FFMA, so the reference-matching chains keep their exact bits at 2x rate.

#define NB    8
#define CH    256
#define NPIX  (NB * 64 * 64)

typedef unsigned long long u64;

__device__ float g_h  [NB * 128 * 128 * CH];  // NHWC h
__device__ float g_ze [NPIX * CH];            // flat z_e rows
__device__ float g_d  [NB * CH * 128 * 128];  // decoder intermediate
__device__ float g_wt [4096 * 256];           // e2 w: [k=(kh*4+kw)*256+ic][oc]
__device__ float g_cn [1024];
__device__ float g_nf [NPIX];
__device__ u64   g_key[NPIX];

// ---- f32x2 helpers (per-lane rn, bit-identical to scalar) ------------------
__device__ __forceinline__ u64 pk2(float lo, float hi) {
    u64 r; asm("mov.b64 %0, {%1, %2};" : "=l"(r) : "f"(lo), "f"(hi)); return r;
}
__device__ __forceinline__ float2 upk2(u64 v) {
    float2 r; asm("mov.b64 {%0, %1}, %2;" : "=f"(r.x), "=f"(r.y) : "l"(v)); return r;
}
__device__ __forceinline__ u64 ffma2(u64 a, u64 b, u64 c) {
    u64 d; asm("fma.rn.f32x2 %0, %1, %2, %3;" : "=l"(d) : "l"(a), "l"(b), "l"(c)); return d;
}
__device__ __forceinline__ u64 fadd2(u64 a, u64 b) {
    u64 d; asm("add.rn.f32x2 %0, %1, %2;" : "=l"(d) : "l"(a), "l"(b)); return d;
}

// ---- key init (every replay; graph-deterministic) --------------------------
__global__ void k_init(int base) {
    g_key[base + blockIdx.x * 256 + threadIdx.x] = ~0ULL;
}

__global__ void k_w2t(const float* __restrict__ w2) {
    int gid = blockIdx.x * 256 + threadIdx.x;     // 1,048,576
    int oc = gid & 255, k = gid >> 8;
    int ic = k & 255, kwh = k >> 8;
    g_wt[gid] = w2[(oc * 256 + ic) * 16 + kwh];
}

// cn: strict scalar sequential (order reference-matching, PASSED)
__global__ void k_cn(const float* __restrict__ cb) {
    int code = blockIdx.x * 32 + threadIdx.x;
    float s = 0.f;
#pragma unroll 8
    for (int c = 0; c < CH; c++) {
        float v = __ldg(cb + code * CH + c);
        s = __fadd_rn(s, __fmul_rn(v, v));
    }
    g_cn[code] = s;
}

// ---- e1: exact chain over (kh,kw); NHWC stores -----------------------------
__global__ __launch_bounds__(256) void k_conv1x(const float* __restrict__ x,
                                                const float* __restrict__ w1,
                                                const float* __restrict__ b1) {
    __shared__ float sx[4][258];
    const int oh = blockIdx.x, b = blockIdx.y, tx = threadIdx.x;
#pragma unroll
    for (int r = 0; r < 4; r++) {
        int ih = 2 * oh - 1 + r;
        for (int c = tx; c < 258; c += 256) {
            int iw = c - 1;
            sx[r][c] = (unsigned(ih) < 256u && unsigned(iw) < 256u)
                           ? x[b * 65536 + ih * 256 + iw] : 0.f;
        }
    }
    __syncthreads();
    const int oc = tx;
    float wreg[16];
#pragma unroll
    for (int t = 0; t < 16; t++) wreg[t] = __ldg(w1 + oc * 16 + t);
    const float bv = __ldg(b1 + oc);
    float* hrow = g_h + (long)((b * 128 + oh) * 128) * 256 + oc;
    for (int ow = 0; ow < 128; ow++) {
        float acc = 0.f;
#pragma unroll
        for (int t = 0; t < 16; t++)
            acc = __fmaf_rn(sx[t >> 2][2 * ow + (t & 3)], wreg[t], acc);
        hrow[(long)ow * 256] = fmaxf(__fadd_rn(acc, bv), 0.f);
    }
}

// ---- e2: exact chains, FFMA2-packed over oc pairs --------------------------
// 64 ow x 64 oc per block at (b,oh); thread = 4 pix x 4 oc (2 oc-pairs).
// k ascending (kh,kw,ic); panel fold (fadd per lane) every 256 (each kh,kw).
__global__ __launch_bounds__(256) void k_conv2x(const float* __restrict__ b2) {
    __shared__ __align__(16) float a_s[64][68];   // [pix][ic]
    __shared__ __align__(16) float w_s[64][68];   // [ic][oc]
    const int ocb = blockIdx.x, oh = blockIdx.y, b = blockIdx.z;
    const int tx = threadIdx.x, i = tx >> 4, j = tx & 15;
    u64 accR[8] = {}, accP[8] = {};               // [p*2+h], h = oc-pair

    for (int kh = 0; kh < 4; kh++) {
        const int ih = 2 * oh - 1 + kh;
        const bool okh = (unsigned(ih) < 128u);
        const long hbase = (long)((b * 128 + ih) * 128) * 256;
        for (int kw = 0; kw < 4; kw++) {
            for (int icb = 0; icb < 4; icb++) {
                __syncthreads();
#pragma unroll
                for (int s = 0; s < 4; s++) {
                    int idx = tx + s * 256, pp = idx >> 4, q = idx & 15;
                    int iw = 2 * pp + kw - 1;
                    float4 v = make_float4(0.f, 0.f, 0.f, 0.f);
                    if (okh && unsigned(iw) < 128u)
                        v = *(const float4*)&g_h[hbase + (long)iw * 256 + icb * 64 + q * 4];
                    *(float4*)&a_s[pp][q * 4] = v;
                }
#pragma unroll
                for (int s = 0; s < 4; s++) {
                    int idx = tx + s * 256, ic = idx >> 4, q = idx & 15;
                    *(float4*)&w_s[ic][q * 4] = *(const float4*)
                        &g_wt[(long)((kh * 4 + kw) * 256 + icb * 64 + ic) * 256 + ocb * 64 + q * 4];
                }
                __syncthreads();
#pragma unroll 4
                for (int ic = 0; ic < 64; ic++) {
                    u64 w01 = *(const u64*)&w_s[ic][j * 4];
                    u64 w23 = *(const u64*)&w_s[ic][j * 4 + 2];
#pragma unroll
                    for (int p = 0; p < 4; p++) {
                        float av = a_s[i * 4 + p][ic];
                        u64 aa = pk2(av, av);
                        accP[p * 2 + 0] = ffma2(aa, w01, accP[p * 2 + 0]);
                        accP[p * 2 + 1] = ffma2(aa, w23, accP[p * 2 + 1]);
                    }
                }
            }
#pragma unroll
            for (int t = 0; t < 8; t++) {         // panel fold (k % 256 == 0)
                accR[t] = fadd2(accR[t], accP[t]);
                accP[t] = 0ULL;
            }
        }
    }
#pragma unroll
    for (int p = 0; p < 4; p++) {
        int pix = ((b * 64 + oh) * 64) + i * 4 + p;
#pragma unroll
        for (int h = 0; h < 2; h++) {
            float2 r = upk2(accR[p * 2 + h]);
            float b0 = __ldg(b2 + ocb * 64 + j * 4 + 2 * h);
            float b1 = __ldg(b2 + ocb * 64 + j * 4 + 2 * h + 1);
            g_ze[(long)pix * 256 + ocb * 64 + j * 4 + 2 * h]     = fmaxf(__fadd_rn(r.x, b0), 0.f);
            g_ze[(long)pix * 256 + ocb * 64 + j * 4 + 2 * h + 1] = fmaxf(__fadd_rn(r.y, b1), 0.f);
        }
    }
}

// ---- ff: 4-lane vector + ordered horizontal (the variant that PASSED) ------
__global__ void k_ff() {
    int pix = blockIdx.x * 256 + threadIdx.x;
    const float* f = g_ze + (long)pix * 256;
    float v[4] = {};
#pragma unroll 8
    for (int i = 0; i < 64; i++) {
#pragma unroll
        for (int l = 0; l < 4; l++) {
            float x = __ldg(f + 4 * i + l);
            v[l] = __fadd_rn(v[l], __fmul_rn(x, x));
        }
    }
    g_nf[pix] = __fadd_rn(__fadd_rn(__fadd_rn(v[0], v[1]), v[2]), v[3]);
}

__device__ __forceinline__ unsigned fkey(float f) {
    unsigned u = __float_as_uint(f);
    return (u & 0x80000000u) ? ~u : (u | 0x80000000u);
}

// ---- fused dot GEMM + bit-exact dist + argmin ------------------------------
// 64 pix x 64 codes per block, K=256 single ascending FMA chain per output
// (FFMA2 over code pairs). d = fadd(fadd(ff, -(2*dot)), cn); key=(fkey(d),code);
// shuffle-reduce over the 16 code-lanes, atomicMin into g_key.
__global__ __launch_bounds__(256) void k_dotvq(const float* __restrict__ cb) {
    __shared__ __align__(16) float As[16][68];
    __shared__ __align__(16) float Bs[16][68];
    __shared__ float cs[64];
    const int n0 = blockIdx.x * 64, py = blockIdx.y;
    const int tx = threadIdx.x, i = tx >> 4, j = tx & 15;
    const float* fl = g_ze + (long)py * 64 * 256;

    if (tx < 64) cs[tx] = __ldg(g_cn + n0 + tx);

    u64 acc[8] = {};                              // [p*2+h], h = code-pair
    for (int kc = 0; kc < 256; kc += 16) {
        __syncthreads();
#pragma unroll
        for (int s = 0; s < 4; s++) {
            int idx = tx + s * 256, p = idx >> 4, k = idx & 15;
            As[k][p] = fl[(long)p * 256 + kc + k];
        }
#pragma unroll
        for (int s = 0; s < 4; s++) {
            int idx = tx + s * 256, n = idx >> 4, k = idx & 15;
            Bs[k][n] = cb[(long)(n0 + n) * 256 + kc + k];
        }
        __syncthreads();
#pragma unroll
        for (int k = 0; k < 16; k++) {
            u64 c01 = *(const u64*)&Bs[k][j * 4];
            u64 c23 = *(const u64*)&Bs[k][j * 4 + 2];
#pragma unroll
            for (int p = 0; p < 4; p++) {
                float av = As[k][i * 4 + p];
                u64 aa = pk2(av, av);
                acc[p * 2 + 0] = ffma2(aa, c01, acc[p * 2 + 0]);
                acc[p * 2 + 1] = ffma2(aa, c23, acc[p * 2 + 1]);
            }
        }
    }

#pragma unroll
    for (int p = 0; p < 4; p++) {
        int pix = py * 64 + i * 4 + p;
        float ff = __ldg(g_nf + pix);
        u64 best = ~0ULL;
#pragma unroll
        for (int h = 0; h < 2; h++) {
            float2 dpair = upk2(acc[p * 2 + h]);
            float dots[2] = {dpair.x, dpair.y};
#pragma unroll
            for (int q = 0; q < 2; q++) {
                int code = n0 + j * 4 + 2 * h + q;
                float t = __fadd_rn(ff, -__fmul_rn(2.f, dots[q]));
                float d = __fadd_rn(t, cs[j * 4 + 2 * h + q]);
                u64 key = ((u64)fkey(d) << 32) | (unsigned)code;
                if (key < best) best = key;
            }
        }
#pragma unroll
        for (int m = 8; m >= 1; m >>= 1) {        // reduce over j lanes only
            u64 o = __shfl_xor_sync(0xffffffffu, best, m);
            if (o < best) best = o;
        }
        if (j == 0) atomicMin(&g_key[pix], best);
    }
}

// ---- z_q gather: planar NCHW into d_out ------------------------------------
__global__ void k_gather(const float* __restrict__ cb, float* __restrict__ zq) {
    int gid = blockIdx.x * 256 + threadIdx.x;     // 8,388,608
    int w = gid & 63, hh = (gid >> 6) & 63, c = (gid >> 12) & 255, b = gid >> 20;
    int pix = (b << 12) | (hh << 6) | w;
    int code = (int)(g_key[pix] & 0xffffffffu);
    zq[gid] = cb[code * CH + c];
}

// ---- d1: ConvT subpixel, FFMA2 over oc pairs, tap-major weights ------------
__global__ __launch_bounds__(256) void k_dconv1(const float* __restrict__ zq,
                                                const float* __restrict__ w,
                                                const float* __restrict__ bias) {
    __shared__ float patch[2][66];
    __shared__ __align__(16) float wst[16][64];   // [tap=kh*4+kw][oc]
    const int oc0 = blockIdx.x * 64, oh = blockIdx.y, b = blockIdx.z;
    const int a = (oh + 1) & 1;
    const int ih1 = (oh + 1 - a) >> 1;
    const int tx = threadIdx.x, i = tx >> 4, j = tx & 15;
    u64 acc[8][2] = {};                           // [pix][oc-pair]

    for (int ic = 0; ic < CH; ic++) {
        __syncthreads();
        if (tx < 132) {
            int r = tx / 66, c = tx - r * 66;
            int ih = ih1 - 1 + r, iw = c - 1;
            patch[r][c] = (unsigned(ih) < 64u && unsigned(iw) < 64u)
                              ? zq[((b * CH + ic) * 64 + ih) * 64 + iw] : 0.f;
        }
        {
            int ocl = tx & 63, kk = (tx >> 6) << 2;
            float4 v = *(const float4*)&w[((ic * CH + oc0 + ocl) << 4) + kk];
            wst[kk + 0][ocl] = v.x; wst[kk + 1][ocl] = v.y;
            wst[kk + 2][ocl] = v.z; wst[kk + 3][ocl] = v.w;
        }
        __syncthreads();

        u64 wA[4][2], wB[4][2];                   // [kw][pair]: kh=a / kh=a+2
#pragma unroll
        for (int kw = 0; kw < 4; kw++) {
            wA[kw][0] = *(const u64*)&wst[a * 4 + kw][j * 4];
            wA[kw][1] = *(const u64*)&wst[a * 4 + kw][j * 4 + 2];
            wB[kw][0] = *(const u64*)&wst[(a + 2) * 4 + kw][j * 4];
            wB[kw][1] = *(const u64*)&wst[(a + 2) * 4 + kw][j * 4 + 2];
        }
        float r0[6], r1[6];
#pragma unroll
        for (int t = 0; t < 6; t++) { r0[t] = patch[0][4 * i + t]; r1[t] = patch[1][4 * i + t]; }
#pragma unroll
        for (int pp = 0; pp < 8; pp++) {
            int lo = (pp + 1) >> 1, hi = lo + 1;
            int kwa = (pp & 1) ? 0 : 1, kwb = kwa + 2;
            u64 vh1 = pk2(r1[hi], r1[hi]), vl1 = pk2(r1[lo], r1[lo]);
            u64 vh0 = pk2(r0[hi], r0[hi]), vl0 = pk2(r0[lo], r0[lo]);
#pragma unroll
            for (int h = 0; h < 2; h++) {
                u64 s = acc[pp][h];
                s = ffma2(vh1, wA[kwa][h], s);
                s = ffma2(vl1, wA[kwb][h], s);
                s = ffma2(vh0, wB[kwa][h], s);
                s = ffma2(vl0, wB[kwb][h], s);
                acc[pp][h] = s;
            }
        }
    }
#pragma unroll
    for (int h = 0; h < 2; h++) {
#pragma unroll
        for (int q = 0; q < 2; q++) {
            int oc = oc0 + j * 4 + 2 * h + q;
            float bv = __ldg(bias + oc);
#pragma unroll
            for (int pp = 0; pp < 8; pp++) {
                float2 r = upk2(acc[pp][h]);
                float val = q ? r.y : r.x;
                g_d[((b * CH + oc) * 128 + oh) * 128 + i * 8 + pp] =
                    fmaxf(val + bv, 0.f);
            }
        }
    }
}

// ---- d2: ConvT 256->1 ------------------------------------------------------
__global__ void k_dconv2(const float* __restrict__ w,
                         const float* __restrict__ bias,
                         float* __restrict__ out) {
    __shared__ float patch[2][132];
    __shared__ float wsh[2][4];
    const int oh = blockIdx.x, b = blockIdx.y;
    const int a = (oh + 1) & 1;
    const int ih1 = (oh + 1 - a) >> 1;
    const int tx = threadIdx.x;
    float acc = 0.f;
    for (int ic = 0; ic < CH; ic++) {
        __syncthreads();
        for (int t = tx; t < 260; t += 256) {
            int r = t / 130, c = t - r * 130;
            int ih = ih1 - 1 + r, iw = c - 1;
            patch[r][c] = (unsigned(ih) < 128u && unsigned(iw) < 128u)
                              ? g_d[((b * CH + ic) * 128 + ih) * 128 + iw] : 0.f;
        }
        if (tx < 8) {
            int r = tx >> 2, k = tx & 3;
            wsh[r][k] = w[ic * 16 + (a + 2 * r) * 4 + k];
        }
        __syncthreads();
        int b0 = 1 - (tx & 1);
        int col = ((tx + 1 - b0) >> 1) + 1;
        acc += patch[1][col] * wsh[0][b0] + patch[1][col - 1] * wsh[0][b0 + 2]
             + patch[0][col] * wsh[1][b0] + patch[0][col - 1] * wsh[1][b0 + 2];
    }
    out[(b << 16) + oh * 256 + tx] = acc + bias[0];
}

extern "C" void kernel_launch(void* const* d_in, const int* in_sizes, int n_in,
                              void* d_out, int out_size) {
    const float* x   = (const float*)d_in[0];
    const float* e1w = (const float*)d_in[1];
    const float* e1b = (const float*)d_in[2];
    const float* e2w = (const float*)d_in[3];
    const float* e2b = (const float*)d_in[4];
    const float* cb  = (const float*)d_in[5];
    const float* d1w = (const float*)d_in[6];
    const float* d1b = (const float*)d_in[7];
    const float* d2w = (const float*)d_in[8];
    const float* d2b = (const float*)d_in[9];
    float* out = (float*)d_out;
    float* zq  = out + NB * 256 * 256;

    // launch order puts k_conv2x 6th so ncu (-s 5 -c 1) captures the e2 mainloop
    k_init  <<<64, 256>>>(0);
    k_init  <<<64, 256>>>(16384);
    k_cn    <<<32, 32>>>(cb);
    k_w2t   <<<4096, 256>>>(e2w);
    k_conv1x<<<dim3(128, NB), 256>>>(x, e1w, e1b);
    k_conv2x<<<dim3(4, 64, NB), 256>>>(e2b);
    k_ff    <<<128, 256>>>();
    k_dotvq <<<dim3(16, 512), 256>>>(cb);
    k_gather<<<32768, 256>>>(cb, zq);
    k_dconv1<<<dim3(4, 128, NB), 256>>>(zq, d1w, d1b);
    k_dconv2<<<dim3(256, NB), 256>>>(d2w, d2b, out);
}